// round 16
// baseline (speedup 1.0000x reference)
#include <cuda_runtime.h>
#include <cuda_bf16.h>
#include <mma.h>
#include <math.h>
#include <stdint.h>

using namespace nvcuda;

// ---------------------------------------------------------------------------
// N=40000, E=640000, C_in=128, C_hid=128, C_out=64, G=64, flat=2904.
// edge_index and batch are int32.
// ---------------------------------------------------------------------------
#define MAXN 40000
#define MAXE 640000
#define NGRAPH 64
#define DPACK 64.0f        // packed degree: v = sum(ew) + 64*count
#define NBPRO 80           // persistent prologue blocks (<=148, all co-resident)
#define CHUNK 512          // nodes per block chunk (80*512 = 40960 >= N)

__device__ float  g_deg[MAXN];          // packed, then dis = rsqrt(sumw+1)
__device__ int    g_counts[MAXN];
__device__ int    g_offsets[MAXN + 1];
__device__ int    g_cursor[MAXN];
__device__ int    g_part[NBPRO];
__device__ float2 g_csr[MAXE];
__device__ __nv_bfloat16 g_xw1b[MAXN * 128];
__device__ __nv_bfloat16 g_xw2b[MAXN * 64];
__device__ float  g_h1 [MAXN * 128];
__device__ float  g_h2 [MAXN * 64];
__device__ float  g_pool[NGRAPH * 64];
__device__ int    g_gstart[NGRAPH + 1];

// grid-wide barrier state (gen monotonic across replays — compared relatively)
__device__ unsigned g_bar_cnt = 0;
__device__ volatile unsigned g_bar_gen = 0;

__device__ __forceinline__ void grid_bar() {
    __syncthreads();
    if (threadIdx.x == 0) {
        unsigned gen = g_bar_gen;
        __threadfence();
        if (atomicAdd(&g_bar_cnt, 1u) == NBPRO - 1) {
            g_bar_cnt = 0;
            __threadfence();
            g_bar_gen = gen + 1;
        } else {
            while (g_bar_gen == gen) { }
        }
    }
    __syncthreads();
}

__device__ __forceinline__ void bf16_split(float v, __nv_bfloat16& h, __nv_bfloat16& l) {
    h = __float2bfloat16_rn(v);
    l = __float2bfloat16_rn(v - __bfloat162float(h));
}

// ---------------------------------------------------------------------------
// Persistent CSR prologue: zero -> degree -> decode/scan -> build, one launch.
// ---------------------------------------------------------------------------
__global__ void prologue_kernel(const int* __restrict__ ei,
                                const float* __restrict__ ew, int N, int E) {
    __shared__ int spine_s[NBPRO];
    __shared__ int warp_sums[8];
    int t = threadIdx.x, b = blockIdx.x;
    int gtid = b * 256 + t, gsz = NBPRO * 256;
    int pairs = (E + 1) / 2;

    // phase 0: zero packed degree
    for (int i = gtid; i < N; i += gsz) g_deg[i] = 0.0f;
    grid_bar();

    // phase 1: packed degree atomics (2 edges / iter, 64-bit loads)
    for (int p = gtid; p < pairs; p += gsz) {
        int e = p * 2;
        int2   c2 = *(const int2*)(ei + E + e);
        float2 w2 = *(const float2*)(ew + e);
        atomicAdd(&g_deg[c2.x], w2.x + DPACK);
        if (e + 1 < E) atomicAdd(&g_deg[c2.y], w2.y + DPACK);
    }
    grid_bar();

    // phase 2: decode counts + dis for my chunk (L1-bypass reads; atomics hit L2)
    int base = b * CHUNK;
    int i0 = base + t * 2, i1 = i0 + 1;
    int v0 = 0, v1 = 0;
    if (i0 < N) {
        float v = __ldcg(&g_deg[i0]);
        int c = (int)(v * (1.0f / DPACK));
        g_counts[i0] = c;
        g_deg[i0] = rsqrtf(v - DPACK * (float)c + 1.0f);
        v0 = c;
    }
    if (i1 < N) {
        float v = __ldcg(&g_deg[i1]);
        int c = (int)(v * (1.0f / DPACK));
        g_counts[i1] = c;
        g_deg[i1] = rsqrtf(v - DPACK * (float)c + 1.0f);
        v1 = c;
    }
    int psum = v0 + v1;
    // block reduce -> g_part[b]
    {
        int s = psum;
        #pragma unroll
        for (int o = 16; o > 0; o >>= 1) s += __shfl_down_sync(0xFFFFFFFFu, s, o);
        if ((t & 31) == 0) warp_sums[t >> 5] = s;
        __syncthreads();
        if (t < 8) {
            int v = warp_sums[t];
            #pragma unroll
            for (int o = 4; o > 0; o >>= 1) v += __shfl_down_sync(0xFFu, v, o);
            if (t == 0) g_part[b] = v;
        }
    }
    grid_bar();

    // phase 3: spine (redundant per block) + block-local scan -> offsets/cursor
    if (t < NBPRO) spine_s[t] = __ldcg(&g_part[t]);
    __syncthreads();
    if (t == 0) {
        int acc = 0;
        #pragma unroll 8
        for (int k = 0; k < NBPRO; k++) { int tmp = spine_s[k]; spine_s[k] = acc; acc += tmp; }
    }
    __syncthreads();
    {
        int lane = t & 31, wid = t >> 5;
        int x = psum;
        #pragma unroll
        for (int o = 1; o < 32; o <<= 1) {
            int y = __shfl_up_sync(0xFFFFFFFFu, x, o);
            if (lane >= o) x += y;
        }
        if (lane == 31) warp_sums[wid] = x;
        __syncthreads();
        if (t < 8) {
            int s = warp_sums[t];
            #pragma unroll
            for (int o = 1; o < 8; o <<= 1) {
                int y = __shfl_up_sync(0xFFu, s, o);
                if (t >= o) s += y;
            }
            warp_sums[t] = s;
        }
        __syncthreads();
        int excl = spine_s[b] + ((wid > 0) ? warp_sums[wid - 1] : 0) + (x - psum);
        if (i0 < N) { g_offsets[i0] = excl; g_cursor[i0] = excl; }
        excl += v0;
        if (i1 < N) { g_offsets[i1] = excl; g_cursor[i1] = excl; }
    }
    if (b == 0 && t == 0) g_offsets[N] = E;
    grid_bar();

    // phase 4: build CSR (dis values from other blocks -> L1-bypass loads)
    for (int p = gtid; p < pairs; p += gsz) {
        int e = p * 2;
        int2   r2 = *(const int2*)(ei + e);
        int2   c2 = *(const int2*)(ei + E + e);
        float2 w2 = *(const float2*)(ew + e);
        {
            int slot = atomicAdd(&g_cursor[c2.x], 1);
            float w = __ldcg(&g_deg[r2.x]) * w2.x * __ldcg(&g_deg[c2.x]);
            g_csr[slot] = make_float2(__int_as_float(r2.x), w);
        }
        if (e + 1 < E) {
            int slot = atomicAdd(&g_cursor[c2.y], 1);
            float w = __ldcg(&g_deg[r2.y]) * w2.y * __ldcg(&g_deg[c2.y]);
            g_csr[slot] = make_float2(__int_as_float(r2.y), w);
        }
    }
}

// ---------------------------------------------------------------------------
// WMMA GEMM (bf16x3): Cb[rows, N_OUT] (bf16) = A[.,128] @ W[128, N_OUT]
// ---------------------------------------------------------------------------
#define ASTR 136
template <int N_OUT>
__global__ void wmma_gemm_kernel(const float* __restrict__ Ain,
                                 const float* __restrict__ W, int M, int base) {
    constexpr int BSTR = (N_OUT == 128) ? 136 : 72;
    constexpr int NFRAG = N_OUT / 32;
    constexpr int CSTR = N_OUT + 4;
    extern __shared__ char smem[];
    __nv_bfloat16* sA_hi = (__nv_bfloat16*)smem;
    __nv_bfloat16* sA_lo = sA_hi + 128 * ASTR;
    __nv_bfloat16* sB_hi = sA_lo + 128 * ASTR;
    __nv_bfloat16* sB_lo = sB_hi + 128 * BSTR;
    float* sC = (float*)smem;

    const float* __restrict__ A = (N_OUT == 128) ? Ain : g_h1;
    __nv_bfloat16* __restrict__ Cb = (N_OUT == 128) ? g_xw1b : g_xw2b;

    int tid = threadIdx.x;
    int row0 = base + blockIdx.x * 128;

    for (int i = tid; i < 128 * 32; i += 256) {
        int row = i >> 5, q = i & 31;
        float4 v = make_float4(0.f, 0.f, 0.f, 0.f);
        if (row0 + row < M)
            v = *(const float4*)(A + (size_t)(row0 + row) * 128 + q * 4);
        float vv[4] = {v.x, v.y, v.z, v.w};
        __nv_bfloat16 h[4], l[4];
        #pragma unroll
        for (int j = 0; j < 4; j++) bf16_split(vv[j], h[j], l[j]);
        int off = row * ASTR + q * 4;
        *(uint2*)(sA_hi + off) = make_uint2(
            ((uint32_t)__bfloat16_as_ushort(h[1]) << 16) | __bfloat16_as_ushort(h[0]),
            ((uint32_t)__bfloat16_as_ushort(h[3]) << 16) | __bfloat16_as_ushort(h[2]));
        *(uint2*)(sA_lo + off) = make_uint2(
            ((uint32_t)__bfloat16_as_ushort(l[1]) << 16) | __bfloat16_as_ushort(l[0]),
            ((uint32_t)__bfloat16_as_ushort(l[3]) << 16) | __bfloat16_as_ushort(l[2]));
    }
    for (int i = tid; i < 128 * (N_OUT / 4); i += 256) {
        int k = i / (N_OUT / 4), qc = i % (N_OUT / 4);
        float4 v = *(const float4*)(W + (size_t)k * N_OUT + qc * 4);
        float vv[4] = {v.x, v.y, v.z, v.w};
        __nv_bfloat16 h[4], l[4];
        #pragma unroll
        for (int j = 0; j < 4; j++) bf16_split(vv[j], h[j], l[j]);
        int off = k * BSTR + qc * 4;
        *(uint2*)(sB_hi + off) = make_uint2(
            ((uint32_t)__bfloat16_as_ushort(h[1]) << 16) | __bfloat16_as_ushort(h[0]),
            ((uint32_t)__bfloat16_as_ushort(h[3]) << 16) | __bfloat16_as_ushort(h[2]));
        *(uint2*)(sB_lo + off) = make_uint2(
            ((uint32_t)__bfloat16_as_ushort(l[1]) << 16) | __bfloat16_as_ushort(l[0]),
            ((uint32_t)__bfloat16_as_ushort(l[3]) << 16) | __bfloat16_as_ushort(l[2]));
    }
    __syncthreads();

    int w  = tid >> 5;
    int mw = w & 3;
    int nw = w >> 2;
    int colb = nw * (N_OUT / 2);

    wmma::fragment<wmma::accumulator, 16, 16, 16, float> acc[2][NFRAG];
    #pragma unroll
    for (int f = 0; f < 2; f++)
        #pragma unroll
        for (int j = 0; j < NFRAG; j++) wmma::fill_fragment(acc[f][j], 0.0f);

    #pragma unroll
    for (int kk = 0; kk < 8; kk++) {
        wmma::fragment<wmma::matrix_a, 16, 16, 16, __nv_bfloat16, wmma::row_major> ah[2], al[2];
        wmma::fragment<wmma::matrix_b, 16, 16, 16, __nv_bfloat16, wmma::row_major> bh[NFRAG], bl[NFRAG];
        #pragma unroll
        for (int f = 0; f < 2; f++) {
            const __nv_bfloat16* pa = sA_hi + (mw * 32 + f * 16) * ASTR + kk * 16;
            wmma::load_matrix_sync(ah[f], pa, ASTR);
            wmma::load_matrix_sync(al[f], pa + 128 * ASTR, ASTR);
        }
        #pragma unroll
        for (int j = 0; j < NFRAG; j++) {
            const __nv_bfloat16* pb = sB_hi + (kk * 16) * BSTR + colb + j * 16;
            wmma::load_matrix_sync(bh[j], pb, BSTR);
            wmma::load_matrix_sync(bl[j], pb + 128 * BSTR, BSTR);
        }
        #pragma unroll
        for (int f = 0; f < 2; f++)
            #pragma unroll
            for (int j = 0; j < NFRAG; j++) {
                wmma::mma_sync(acc[f][j], ah[f], bh[j], acc[f][j]);
                wmma::mma_sync(acc[f][j], ah[f], bl[j], acc[f][j]);
                wmma::mma_sync(acc[f][j], al[f], bh[j], acc[f][j]);
            }
    }

    __syncthreads();
    #pragma unroll
    for (int f = 0; f < 2; f++)
        #pragma unroll
        for (int j = 0; j < NFRAG; j++)
            wmma::store_matrix_sync(
                sC + (size_t)(mw * 32 + f * 16) * CSTR + colb + j * 16,
                acc[f][j], CSTR, wmma::mem_row_major);
    __syncthreads();
    for (int i = tid; i < 128 * (N_OUT / 4); i += 256) {
        int row = i / (N_OUT / 4), qc = i % (N_OUT / 4);
        if (row0 + row < M) {
            float4 v = *(float4*)(sC + (size_t)row * CSTR + qc * 4);
            __nv_bfloat162 b0 = __float22bfloat162_rn(make_float2(v.x, v.y));
            __nv_bfloat162 b1 = __float22bfloat162_rn(make_float2(v.z, v.w));
            *(uint2*)(Cb + (size_t)(row0 + row) * N_OUT + qc * 4) =
                make_uint2(*(uint32_t*)&b0, *(uint32_t*)&b1);
        }
    }
}
#define WMMA_SMEM_128 (4 * 128 * 136 * 2)
#define WMMA_SMEM_64  (2 * 128 * 136 * 2 + 2 * 128 * 72 * 2)

// ---------------------------------------------------------------------------
// Gather (bf16 src) + self-loop + bias + ReLU -> fp32. Warp per node.
// ---------------------------------------------------------------------------
__device__ __forceinline__ float4 ld_bf16x4(const __nv_bfloat16* p) {
    uint2 u = *(const uint2*)p;
    __nv_bfloat162 a = *(__nv_bfloat162*)&u.x;
    __nv_bfloat162 b = *(__nv_bfloat162*)&u.y;
    float2 fa = __bfloat1622float2(a);
    float2 fb = __bfloat1622float2(b);
    return make_float4(fa.x, fa.y, fb.x, fb.y);
}
__device__ __forceinline__ float2 ld_bf16x2(const __nv_bfloat16* p) {
    uint32_t u = *(const uint32_t*)p;
    return __bfloat1622float2(*(__nv_bfloat162*)&u);
}

template <int F>
__global__ void gather_kernel(const float* __restrict__ bias, int base, int count, int M) {
    const __nv_bfloat16* __restrict__ xw = (F == 128) ? g_xw1b : g_xw2b;
    float* __restrict__ outp = (F == 128) ? g_h1 : g_h2;
    int gid = (blockIdx.x * blockDim.x + threadIdx.x) >> 5;
    int lane = threadIdx.x & 31;
    if (gid >= count) return;
    int warp = base + gid;
    if (warp >= M) return;
    int s = g_offsets[warp];
    int e = g_offsets[warp + 1];

    if (F == 128) {
        float4 acc = make_float4(0.f, 0.f, 0.f, 0.f);
        int i = s;
        for (; i + 3 < e; i += 4) {
            float2 p0 = g_csr[i],     p1 = g_csr[i + 1];
            float2 p2 = g_csr[i + 2], p3 = g_csr[i + 3];
            float4 x0 = ld_bf16x4(xw + (size_t)__float_as_int(p0.x) * 128 + lane * 4);
            float4 x1 = ld_bf16x4(xw + (size_t)__float_as_int(p1.x) * 128 + lane * 4);
            float4 x2 = ld_bf16x4(xw + (size_t)__float_as_int(p2.x) * 128 + lane * 4);
            float4 x3 = ld_bf16x4(xw + (size_t)__float_as_int(p3.x) * 128 + lane * 4);
            acc.x = fmaf(p0.y, x0.x, acc.x); acc.y = fmaf(p0.y, x0.y, acc.y);
            acc.z = fmaf(p0.y, x0.z, acc.z); acc.w = fmaf(p0.y, x0.w, acc.w);
            acc.x = fmaf(p1.y, x1.x, acc.x); acc.y = fmaf(p1.y, x1.y, acc.y);
            acc.z = fmaf(p1.y, x1.z, acc.z); acc.w = fmaf(p1.y, x1.w, acc.w);
            acc.x = fmaf(p2.y, x2.x, acc.x); acc.y = fmaf(p2.y, x2.y, acc.y);
            acc.z = fmaf(p2.y, x2.z, acc.z); acc.w = fmaf(p2.y, x2.w, acc.w);
            acc.x = fmaf(p3.y, x3.x, acc.x); acc.y = fmaf(p3.y, x3.y, acc.y);
            acc.z = fmaf(p3.y, x3.z, acc.z); acc.w = fmaf(p3.y, x3.w, acc.w);
        }
        for (; i < e; i++) {
            float2 p0 = g_csr[i];
            float4 x0 = ld_bf16x4(xw + (size_t)__float_as_int(p0.x) * 128 + lane * 4);
            acc.x = fmaf(p0.y, x0.x, acc.x); acc.y = fmaf(p0.y, x0.y, acc.y);
            acc.z = fmaf(p0.y, x0.z, acc.z); acc.w = fmaf(p0.y, x0.w, acc.w);
        }
        float d  = g_deg[warp];
        float d2 = d * d;
        float4 sf = ld_bf16x4(xw + (size_t)warp * 128 + lane * 4);
        float4 bb = *(const float4*)(bias + lane * 4);
        float4 r;
        r.x = fmaxf(fmaf(sf.x, d2, acc.x) + bb.x, 0.f);
        r.y = fmaxf(fmaf(sf.y, d2, acc.y) + bb.y, 0.f);
        r.z = fmaxf(fmaf(sf.z, d2, acc.z) + bb.z, 0.f);
        r.w = fmaxf(fmaf(sf.w, d2, acc.w) + bb.w, 0.f);
        *(float4*)(outp + (size_t)warp * 128 + lane * 4) = r;
    } else {
        float2 acc = make_float2(0.f, 0.f);
        int i = s;
        for (; i + 3 < e; i += 4) {
            float2 p0 = g_csr[i],     p1 = g_csr[i + 1];
            float2 p2 = g_csr[i + 2], p3 = g_csr[i + 3];
            float2 x0 = ld_bf16x2(xw + (size_t)__float_as_int(p0.x) * 64 + lane * 2);
            float2 x1 = ld_bf16x2(xw + (size_t)__float_as_int(p1.x) * 64 + lane * 2);
            float2 x2 = ld_bf16x2(xw + (size_t)__float_as_int(p2.x) * 64 + lane * 2);
            float2 x3 = ld_bf16x2(xw + (size_t)__float_as_int(p3.x) * 64 + lane * 2);
            acc.x = fmaf(p0.y, x0.x, acc.x); acc.y = fmaf(p0.y, x0.y, acc.y);
            acc.x = fmaf(p1.y, x1.x, acc.x); acc.y = fmaf(p1.y, x1.y, acc.y);
            acc.x = fmaf(p2.y, x2.x, acc.x); acc.y = fmaf(p2.y, x2.y, acc.y);
            acc.x = fmaf(p3.y, x3.x, acc.x); acc.y = fmaf(p3.y, x3.y, acc.y);
        }
        for (; i < e; i++) {
            float2 p0 = g_csr[i];
            float2 x0 = ld_bf16x2(xw + (size_t)__float_as_int(p0.x) * 64 + lane * 2);
            acc.x = fmaf(p0.y, x0.x, acc.x); acc.y = fmaf(p0.y, x0.y, acc.y);
        }
        float d  = g_deg[warp];
        float d2 = d * d;
        float2 sf = ld_bf16x2(xw + (size_t)warp * 64 + lane * 2);
        float2 bb = *(const float2*)(bias + lane * 2);
        float2 r;
        r.x = fmaxf(fmaf(sf.x, d2, acc.x) + bb.x, 0.f);
        r.y = fmaxf(fmaf(sf.y, d2, acc.y) + bb.y, 0.f);
        *(float2*)(outp + (size_t)warp * 64 + lane * 2) = r;
    }
}

// ---------------------------------------------------------------------------
__global__ void bounds_kernel(const int* __restrict__ batch, int N) {
    int g = threadIdx.x;
    if (g > NGRAPH) return;
    int lo = 0, hi = N;
    while (lo < hi) {
        int mid = (lo + hi) >> 1;
        if (batch[mid] < g) lo = mid + 1; else hi = mid;
    }
    g_gstart[g] = lo;
}

__global__ void pool_kernel() {
    int g = blockIdx.x;
    int t = threadIdx.x;
    int f   = t & 63;
    int sub = t >> 6;
    int s = g_gstart[g], e = g_gstart[g + 1];
    float acc = 0.0f;
    for (int i = s + sub; i < e; i += 4)
        acc += g_h2[(size_t)i * 64 + f];
    __shared__ float red[256];
    red[t] = acc;
    __syncthreads();
    if (t < 64) {
        float v = red[t] + red[t + 64] + red[t + 128] + red[t + 192];
        float cnt = (float)(e - s);
        g_pool[g * 64 + t] = v / fmaxf(cnt, 1.0f);
    }
}

__global__ void fc_kernel(const float* __restrict__ Wfc,
                          const float* __restrict__ bfc,
                          float* __restrict__ out, int flat) {
    int idx = blockIdx.x * blockDim.x + threadIdx.x;
    int tot = NGRAPH * flat;
    if (idx >= tot) return;
    int g = idx / flat;
    int j = idx - g * flat;
    const float* pg = g_pool + g * 64;
    float s = bfc[j];
    #pragma unroll 8
    for (int k = 0; k < 64; k++)
        s = fmaf(pg[k], Wfc[(size_t)k * flat + j], s);
    out[idx] = s;
}

// ---------------------------------------------------------------------------
// Static resources (created at load time — NOT during capture)
// ---------------------------------------------------------------------------
static cudaStream_t g_s2;
static cudaEvent_t  g_evFork, g_evJoin, g_evG1A, g_evGemm2A;
namespace {
struct StreamInit {
    StreamInit() {
        cudaStreamCreateWithFlags(&g_s2, cudaStreamNonBlocking);
        cudaEventCreateWithFlags(&g_evFork, cudaEventDisableTiming);
        cudaEventCreateWithFlags(&g_evJoin, cudaEventDisableTiming);
        cudaEventCreateWithFlags(&g_evG1A, cudaEventDisableTiming);
        cudaEventCreateWithFlags(&g_evGemm2A, cudaEventDisableTiming);
        cudaFuncSetAttribute(wmma_gemm_kernel<128>,
                             cudaFuncAttributeMaxDynamicSharedMemorySize, WMMA_SMEM_128);
        cudaFuncSetAttribute(wmma_gemm_kernel<64>,
                             cudaFuncAttributeMaxDynamicSharedMemorySize, WMMA_SMEM_64);
    }
};
static StreamInit g_streamInit;
}

// ---------------------------------------------------------------------------
extern "C" void kernel_launch(void* const* d_in, const int* in_sizes, int n_in,
                              void* d_out, int out_size) {
    const float* x     = (const float*)d_in[0];
    const int*   ei    = (const int*)d_in[1];
    const float* ew    = (const float*)d_in[2];
    const int*   batch = (const int*)d_in[3];
    const float* W1    = (const float*)d_in[4];
    const float* b1    = (const float*)d_in[5];
    const float* W2    = (const float*)d_in[6];
    const float* b2    = (const float*)d_in[7];
    const float* Wfc   = (const float*)d_in[8];
    const float* bfc   = (const float*)d_in[9];
    float* out = (float*)d_out;

    int N    = in_sizes[0] / 128;   // 40000
    int E    = in_sizes[2];         // 640000
    int flat = in_sizes[8] / 64;    // 2904
    int tb = 256;
    int ngrid = (N + 127) / 128;    // 313

    int gridA = (ngrid + 1) / 2;    // 157
    int MA    = gridA * 128;        // 20096
    int gridB = ngrid - gridA;      // 156
    int MB    = N - MA;             // 19904

    // ---- fork: GEMM1 + bounds on s2, persistent CSR prologue on default ----
    cudaEventRecord(g_evFork, 0);
    cudaStreamWaitEvent(g_s2, g_evFork, 0);

    bounds_kernel<<<1, 128, 0, g_s2>>>(batch, N);
    wmma_gemm_kernel<128><<<ngrid, 256, WMMA_SMEM_128, g_s2>>>(x, W1, N, 0);

    prologue_kernel<<<NBPRO, 256>>>(ei, ew, N, E);

    cudaEventRecord(g_evJoin, g_s2);
    cudaStreamWaitEvent(0, g_evJoin, 0);

    // ---- layer 1 aggregate / layer 2 GEMM pipeline ----
    gather_kernel<128><<<(MA + 7) / 8, 256>>>(b1, 0, MA, N);
    cudaEventRecord(g_evG1A, 0);
    cudaStreamWaitEvent(g_s2, g_evG1A, 0);
    wmma_gemm_kernel<64><<<gridA, 256, WMMA_SMEM_64, g_s2>>>(nullptr, W2, N, 0);
    cudaEventRecord(g_evGemm2A, g_s2);

    gather_kernel<128><<<(MB + 7) / 8, 256>>>(b1, MA, MB, N);
    wmma_gemm_kernel<64><<<gridB, 256, WMMA_SMEM_64>>>(nullptr, W2, N, MA);
    cudaStreamWaitEvent(0, g_evGemm2A, 0);

    // ---- layer 2 aggregate, pool, fc ----
    gather_kernel<64><<<(N + 7) / 8, 256>>>(b2, 0, N, N);
    pool_kernel<<<NGRAPH, 256>>>();
    fc_kernel<<<(NGRAPH * flat + tb - 1) / tb, tb>>>(Wfc, bfc, out, flat);
}

// round 17
// speedup vs baseline: 1.1499x; 1.1499x over previous
#include <cuda_runtime.h>
#include <cuda_bf16.h>
#include <mma.h>
#include <math.h>
#include <stdint.h>

using namespace nvcuda;

// ---------------------------------------------------------------------------
// N=40000, E=640000, C_in=128, C_hid=128, C_out=64, G=64, flat=2904.
// edge_index and batch are int32.
// ---------------------------------------------------------------------------
#define MAXN 40000
#define MAXE 640000
#define NGRAPH 64
#define SCAN_CHUNK 1024
#define MAXPART 64
#define DPACK 64.0f        // packed degree: v = sum(ew) + 64*count

__device__ float  g_deg[MAXN];          // packed, then dis = rsqrt(sumw+1)
__device__ int    g_counts[MAXN];
__device__ int    g_offsets[MAXN + 1];
__device__ int    g_cursor[MAXN];
__device__ int    g_part[MAXPART];
__device__ float2 g_csr[MAXE];
__device__ __nv_bfloat16 g_xw1b[MAXN * 128];   // GEMM1 out (bf16, gather1 src)
__device__ __nv_bfloat16 g_h1b [MAXN * 128];   // gather1 out (bf16, GEMM2 A)
__device__ __nv_bfloat16 g_xw2b[MAXN * 64];    // GEMM2 out (bf16, gather2 src)
__device__ float  g_h2 [MAXN * 64];            // gather2 out (fp32, pool in)
__device__ float  g_pool[NGRAPH * 64];
__device__ int    g_gstart[NGRAPH + 1];

__device__ __forceinline__ void bf16_split(float v, __nv_bfloat16& h, __nv_bfloat16& l) {
    h = __float2bfloat16_rn(v);
    l = __float2bfloat16_rn(v - __bfloat162float(h));
}

// ---------------------------------------------------------------------------
// WMMA GEMM: Cb[rows, N_OUT] (bf16) = A[.,128] @ W[128, N_OUT]
// N_OUT=128: A = external x (fp32, bf16x3 split), dst = g_xw1b.
// N_OUT=64 : A = g_h1b (already bf16, NO split -> 2 MMAs/step), dst = g_xw2b.
// ---------------------------------------------------------------------------
#define ASTR 136
template <int N_OUT>
__global__ void wmma_gemm_kernel(const float* __restrict__ Ain,
                                 const float* __restrict__ W, int M, int base) {
    constexpr bool ABF = (N_OUT == 64);          // A already bf16
    constexpr int BSTR = (N_OUT == 128) ? 136 : 72;
    constexpr int NFRAG = N_OUT / 32;
    constexpr int CSTR = N_OUT + 4;
    extern __shared__ char smem[];
    __nv_bfloat16* sA_hi = (__nv_bfloat16*)smem;
    __nv_bfloat16* sA_lo = sA_hi + 128 * ASTR;   // unused when ABF
    __nv_bfloat16* sB_hi = sA_hi + (ABF ? 1 : 2) * 128 * ASTR;
    __nv_bfloat16* sB_lo = sB_hi + 128 * BSTR;
    float* sC = (float*)smem;

    __nv_bfloat16* __restrict__ Cb = (N_OUT == 128) ? g_xw1b : g_xw2b;

    int tid = threadIdx.x;
    int row0 = base + blockIdx.x * 128;

    if (ABF) {
        // A fill: copy bf16 rows straight into smem
        for (int i = tid; i < 128 * 32; i += 256) {
            int row = i >> 5, q = i & 31;
            uint2 v = make_uint2(0u, 0u);
            if (row0 + row < M)
                v = *(const uint2*)(g_h1b + (size_t)(row0 + row) * 128 + q * 4);
            *(uint2*)(sA_hi + row * ASTR + q * 4) = v;
        }
    } else {
        for (int i = tid; i < 128 * 32; i += 256) {
            int row = i >> 5, q = i & 31;
            float4 v = make_float4(0.f, 0.f, 0.f, 0.f);
            if (row0 + row < M)
                v = *(const float4*)(Ain + (size_t)(row0 + row) * 128 + q * 4);
            float vv[4] = {v.x, v.y, v.z, v.w};
            __nv_bfloat16 h[4], l[4];
            #pragma unroll
            for (int j = 0; j < 4; j++) bf16_split(vv[j], h[j], l[j]);
            int off = row * ASTR + q * 4;
            *(uint2*)(sA_hi + off) = make_uint2(
                ((uint32_t)__bfloat16_as_ushort(h[1]) << 16) | __bfloat16_as_ushort(h[0]),
                ((uint32_t)__bfloat16_as_ushort(h[3]) << 16) | __bfloat16_as_ushort(h[2]));
            *(uint2*)(sA_lo + off) = make_uint2(
                ((uint32_t)__bfloat16_as_ushort(l[1]) << 16) | __bfloat16_as_ushort(l[0]),
                ((uint32_t)__bfloat16_as_ushort(l[3]) << 16) | __bfloat16_as_ushort(l[2]));
        }
    }
    for (int i = tid; i < 128 * (N_OUT / 4); i += 256) {
        int k = i / (N_OUT / 4), qc = i % (N_OUT / 4);
        float4 v = *(const float4*)(W + (size_t)k * N_OUT + qc * 4);
        float vv[4] = {v.x, v.y, v.z, v.w};
        __nv_bfloat16 h[4], l[4];
        #pragma unroll
        for (int j = 0; j < 4; j++) bf16_split(vv[j], h[j], l[j]);
        int off = k * BSTR + qc * 4;
        *(uint2*)(sB_hi + off) = make_uint2(
            ((uint32_t)__bfloat16_as_ushort(h[1]) << 16) | __bfloat16_as_ushort(h[0]),
            ((uint32_t)__bfloat16_as_ushort(h[3]) << 16) | __bfloat16_as_ushort(h[2]));
        *(uint2*)(sB_lo + off) = make_uint2(
            ((uint32_t)__bfloat16_as_ushort(l[1]) << 16) | __bfloat16_as_ushort(l[0]),
            ((uint32_t)__bfloat16_as_ushort(l[3]) << 16) | __bfloat16_as_ushort(l[2]));
    }
    __syncthreads();

    int w  = tid >> 5;
    int mw = w & 3;
    int nw = w >> 2;
    int colb = nw * (N_OUT / 2);

    wmma::fragment<wmma::accumulator, 16, 16, 16, float> acc[2][NFRAG];
    #pragma unroll
    for (int f = 0; f < 2; f++)
        #pragma unroll
        for (int j = 0; j < NFRAG; j++) wmma::fill_fragment(acc[f][j], 0.0f);

    #pragma unroll
    for (int kk = 0; kk < 8; kk++) {
        wmma::fragment<wmma::matrix_a, 16, 16, 16, __nv_bfloat16, wmma::row_major> ah[2], al[2];
        wmma::fragment<wmma::matrix_b, 16, 16, 16, __nv_bfloat16, wmma::row_major> bh[NFRAG], bl[NFRAG];
        #pragma unroll
        for (int f = 0; f < 2; f++) {
            const __nv_bfloat16* pa = sA_hi + (mw * 32 + f * 16) * ASTR + kk * 16;
            wmma::load_matrix_sync(ah[f], pa, ASTR);
            if (!ABF) wmma::load_matrix_sync(al[f], pa + 128 * ASTR, ASTR);
        }
        #pragma unroll
        for (int j = 0; j < NFRAG; j++) {
            const __nv_bfloat16* pb = sB_hi + (kk * 16) * BSTR + colb + j * 16;
            wmma::load_matrix_sync(bh[j], pb, BSTR);
            wmma::load_matrix_sync(bl[j], pb + 128 * BSTR, BSTR);
        }
        #pragma unroll
        for (int f = 0; f < 2; f++)
            #pragma unroll
            for (int j = 0; j < NFRAG; j++) {
                wmma::mma_sync(acc[f][j], ah[f], bh[j], acc[f][j]);
                wmma::mma_sync(acc[f][j], ah[f], bl[j], acc[f][j]);
                if (!ABF) wmma::mma_sync(acc[f][j], al[f], bh[j], acc[f][j]);
            }
    }

    __syncthreads();
    #pragma unroll
    for (int f = 0; f < 2; f++)
        #pragma unroll
        for (int j = 0; j < NFRAG; j++)
            wmma::store_matrix_sync(
                sC + (size_t)(mw * 32 + f * 16) * CSTR + colb + j * 16,
                acc[f][j], CSTR, wmma::mem_row_major);
    __syncthreads();
    for (int i = tid; i < 128 * (N_OUT / 4); i += 256) {
        int row = i / (N_OUT / 4), qc = i % (N_OUT / 4);
        if (row0 + row < M) {
            float4 v = *(float4*)(sC + (size_t)row * CSTR + qc * 4);
            __nv_bfloat162 b0 = __float22bfloat162_rn(make_float2(v.x, v.y));
            __nv_bfloat162 b1 = __float22bfloat162_rn(make_float2(v.z, v.w));
            *(uint2*)(Cb + (size_t)(row0 + row) * N_OUT + qc * 4) =
                make_uint2(*(uint32_t*)&b0, *(uint32_t*)&b1);
        }
    }
}
#define WMMA_SMEM_128 (4 * 128 * 136 * 2)
#define WMMA_SMEM_64  ((128 * 136 + 2 * 128 * 72) * 2)

// ---------------------------------------------------------------------------
__global__ void zero_kernel(int n) {
    int i = blockIdx.x * blockDim.x + threadIdx.x;
    if (i < n) g_deg[i] = 0.0f;
}

// single fast-class fp32 atomic per edge; 2 edges per thread via 64-bit loads
__global__ void degree_kernel(const int* __restrict__ ei,
                              const float* __restrict__ ew, int E) {
    int p = blockIdx.x * blockDim.x + threadIdx.x;
    int e = p * 2;
    if (e >= E) return;
    int2   c2 = *(const int2*)(ei + E + e);
    float2 w2 = *(const float2*)(ew + e);
    atomicAdd(&g_deg[c2.x], w2.x + DPACK);
    if (e + 1 < E) atomicAdd(&g_deg[c2.y], w2.y + DPACK);
}

// decode packed degree -> counts + dis, plus per-chunk count sums
__global__ void scan_part_kernel(int n) {
    __shared__ int warp_sums[8];
    int t = threadIdx.x;
    int base = blockIdx.x * SCAN_CHUNK;
    int s = 0;
    #pragma unroll
    for (int j = 0; j < 4; j++) {
        int idx = base + t * 4 + j;
        if (idx < n) {
            float v = g_deg[idx];
            int c = (int)(v * (1.0f / DPACK));
            float sw = v - DPACK * (float)c;
            g_counts[idx] = c;
            g_deg[idx] = rsqrtf(sw + 1.0f);
            s += c;
        }
    }
    #pragma unroll
    for (int o = 16; o > 0; o >>= 1) s += __shfl_down_sync(0xFFFFFFFFu, s, o);
    if ((t & 31) == 0) warp_sums[t >> 5] = s;
    __syncthreads();
    if (t < 8) {
        int v = warp_sums[t];
        #pragma unroll
        for (int o = 4; o > 0; o >>= 1) v += __shfl_down_sync(0xFFu, v, o);
        if (t == 0) g_part[blockIdx.x] = v;
    }
}

__global__ void scan_final_kernel(int npart, int n, int E) {
    __shared__ int warp_sums[8];
    __shared__ int spine[MAXPART];
    int t = threadIdx.x, lane = t & 31, wid = t >> 5;

    if (t < 32) {
        int a = (t * 2     < npart) ? g_part[t * 2]     : 0;
        int b = (t * 2 + 1 < npart) ? g_part[t * 2 + 1] : 0;
        int s = a + b;
        int x = s;
        #pragma unroll
        for (int o = 1; o < 32; o <<= 1) {
            int y = __shfl_up_sync(0xFFFFFFFFu, x, o);
            if (t >= o) x += y;
        }
        int excl = x - s;
        spine[t * 2]     = excl;
        spine[t * 2 + 1] = excl + a;
    }
    __syncthreads();

    int base = blockIdx.x * SCAN_CHUNK;
    int v[4], p = 0;
    #pragma unroll
    for (int j = 0; j < 4; j++) {
        int idx = base + t * 4 + j;
        v[j] = (idx < n) ? g_counts[idx] : 0;
        p += v[j];
    }
    int x = p;
    #pragma unroll
    for (int o = 1; o < 32; o <<= 1) {
        int y = __shfl_up_sync(0xFFFFFFFFu, x, o);
        if (lane >= o) x += y;
    }
    if (lane == 31) warp_sums[wid] = x;
    __syncthreads();
    if (t < 8) {
        int s = warp_sums[t];
        #pragma unroll
        for (int o = 1; o < 8; o <<= 1) {
            int y = __shfl_up_sync(0xFFu, s, o);
            if (t >= o) s += y;
        }
        warp_sums[t] = s;
    }
    __syncthreads();
    int bexcl = spine[blockIdx.x] + ((wid > 0) ? warp_sums[wid - 1] : 0) + (x - p);
    #pragma unroll
    for (int j = 0; j < 4; j++) {
        int idx = base + t * 4 + j;
        if (idx < n) { g_offsets[idx] = bexcl; g_cursor[idx] = bexcl; }
        bexcl += v[j];
    }
    if (blockIdx.x == 0 && t == 0) g_offsets[n] = E;
}

// 2 edges per thread via 64-bit loads
__global__ void build_kernel(const int* __restrict__ ei,
                             const float* __restrict__ ew, int E) {
    int p = blockIdx.x * blockDim.x + threadIdx.x;
    int e = p * 2;
    if (e >= E) return;
    int2   r2 = *(const int2*)(ei + e);
    int2   c2 = *(const int2*)(ei + E + e);
    float2 w2 = *(const float2*)(ew + e);
    {
        int slot = atomicAdd(&g_cursor[c2.x], 1);
        float w = g_deg[r2.x] * w2.x * g_deg[c2.x];
        g_csr[slot] = make_float2(__int_as_float(r2.x), w);
    }
    if (e + 1 < E) {
        int slot = atomicAdd(&g_cursor[c2.y], 1);
        float w = g_deg[r2.y] * w2.y * g_deg[c2.y];
        g_csr[slot] = make_float2(__int_as_float(r2.y), w);
    }
}

// ---------------------------------------------------------------------------
// Gather (bf16 src) + self-loop + bias + ReLU. Warp per node.
// F=128: dst = g_h1b (bf16).  F=64: dst = g_h2 (fp32).
// ---------------------------------------------------------------------------
__device__ __forceinline__ float4 ld_bf16x4(const __nv_bfloat16* p) {
    uint2 u = *(const uint2*)p;
    __nv_bfloat162 a = *(__nv_bfloat162*)&u.x;
    __nv_bfloat162 b = *(__nv_bfloat162*)&u.y;
    float2 fa = __bfloat1622float2(a);
    float2 fb = __bfloat1622float2(b);
    return make_float4(fa.x, fa.y, fb.x, fb.y);
}
__device__ __forceinline__ float2 ld_bf16x2(const __nv_bfloat16* p) {
    uint32_t u = *(const uint32_t*)p;
    return __bfloat1622float2(*(__nv_bfloat162*)&u);
}

template <int F>
__global__ void gather_kernel(const float* __restrict__ bias, int base, int count, int M) {
    const __nv_bfloat16* __restrict__ xw = (F == 128) ? g_xw1b : g_xw2b;
    int gid = (blockIdx.x * blockDim.x + threadIdx.x) >> 5;
    int lane = threadIdx.x & 31;
    if (gid >= count) return;
    int warp = base + gid;
    if (warp >= M) return;
    int s = g_offsets[warp];
    int e = g_offsets[warp + 1];

    if (F == 128) {
        float4 acc = make_float4(0.f, 0.f, 0.f, 0.f);
        int i = s;
        for (; i + 3 < e; i += 4) {
            float2 p0 = g_csr[i],     p1 = g_csr[i + 1];
            float2 p2 = g_csr[i + 2], p3 = g_csr[i + 3];
            float4 x0 = ld_bf16x4(xw + (size_t)__float_as_int(p0.x) * 128 + lane * 4);
            float4 x1 = ld_bf16x4(xw + (size_t)__float_as_int(p1.x) * 128 + lane * 4);
            float4 x2 = ld_bf16x4(xw + (size_t)__float_as_int(p2.x) * 128 + lane * 4);
            float4 x3 = ld_bf16x4(xw + (size_t)__float_as_int(p3.x) * 128 + lane * 4);
            acc.x = fmaf(p0.y, x0.x, acc.x); acc.y = fmaf(p0.y, x0.y, acc.y);
            acc.z = fmaf(p0.y, x0.z, acc.z); acc.w = fmaf(p0.y, x0.w, acc.w);
            acc.x = fmaf(p1.y, x1.x, acc.x); acc.y = fmaf(p1.y, x1.y, acc.y);
            acc.z = fmaf(p1.y, x1.z, acc.z); acc.w = fmaf(p1.y, x1.w, acc.w);
            acc.x = fmaf(p2.y, x2.x, acc.x); acc.y = fmaf(p2.y, x2.y, acc.y);
            acc.z = fmaf(p2.y, x2.z, acc.z); acc.w = fmaf(p2.y, x2.w, acc.w);
            acc.x = fmaf(p3.y, x3.x, acc.x); acc.y = fmaf(p3.y, x3.y, acc.y);
            acc.z = fmaf(p3.y, x3.z, acc.z); acc.w = fmaf(p3.y, x3.w, acc.w);
        }
        for (; i < e; i++) {
            float2 p0 = g_csr[i];
            float4 x0 = ld_bf16x4(xw + (size_t)__float_as_int(p0.x) * 128 + lane * 4);
            acc.x = fmaf(p0.y, x0.x, acc.x); acc.y = fmaf(p0.y, x0.y, acc.y);
            acc.z = fmaf(p0.y, x0.z, acc.z); acc.w = fmaf(p0.y, x0.w, acc.w);
        }
        float d  = g_deg[warp];
        float d2 = d * d;
        float4 sf = ld_bf16x4(xw + (size_t)warp * 128 + lane * 4);
        float4 bb = *(const float4*)(bias + lane * 4);
        float4 r;
        r.x = fmaxf(fmaf(sf.x, d2, acc.x) + bb.x, 0.f);
        r.y = fmaxf(fmaf(sf.y, d2, acc.y) + bb.y, 0.f);
        r.z = fmaxf(fmaf(sf.z, d2, acc.z) + bb.z, 0.f);
        r.w = fmaxf(fmaf(sf.w, d2, acc.w) + bb.w, 0.f);
        __nv_bfloat162 o0 = __float22bfloat162_rn(make_float2(r.x, r.y));
        __nv_bfloat162 o1 = __float22bfloat162_rn(make_float2(r.z, r.w));
        *(uint2*)(g_h1b + (size_t)warp * 128 + lane * 4) =
            make_uint2(*(uint32_t*)&o0, *(uint32_t*)&o1);
    } else {
        float2 acc = make_float2(0.f, 0.f);
        int i = s;
        for (; i + 3 < e; i += 4) {
            float2 p0 = g_csr[i],     p1 = g_csr[i + 1];
            float2 p2 = g_csr[i + 2], p3 = g_csr[i + 3];
            float2 x0 = ld_bf16x2(xw + (size_t)__float_as_int(p0.x) * 64 + lane * 2);
            float2 x1 = ld_bf16x2(xw + (size_t)__float_as_int(p1.x) * 64 + lane * 2);
            float2 x2 = ld_bf16x2(xw + (size_t)__float_as_int(p2.x) * 64 + lane * 2);
            float2 x3 = ld_bf16x2(xw + (size_t)__float_as_int(p3.x) * 64 + lane * 2);
            acc.x = fmaf(p0.y, x0.x, acc.x); acc.y = fmaf(p0.y, x0.y, acc.y);
            acc.x = fmaf(p1.y, x1.x, acc.x); acc.y = fmaf(p1.y, x1.y, acc.y);
            acc.x = fmaf(p2.y, x2.x, acc.x); acc.y = fmaf(p2.y, x2.y, acc.y);
            acc.x = fmaf(p3.y, x3.x, acc.x); acc.y = fmaf(p3.y, x3.y, acc.y);
        }
        for (; i < e; i++) {
            float2 p0 = g_csr[i];
            float2 x0 = ld_bf16x2(xw + (size_t)__float_as_int(p0.x) * 64 + lane * 2);
            acc.x = fmaf(p0.y, x0.x, acc.x); acc.y = fmaf(p0.y, x0.y, acc.y);
        }
        float d  = g_deg[warp];
        float d2 = d * d;
        float2 sf = ld_bf16x2(xw + (size_t)warp * 64 + lane * 2);
        float2 bb = *(const float2*)(bias + lane * 2);
        float2 r;
        r.x = fmaxf(fmaf(sf.x, d2, acc.x) + bb.x, 0.f);
        r.y = fmaxf(fmaf(sf.y, d2, acc.y) + bb.y, 0.f);
        *(float2*)(g_h2 + (size_t)warp * 64 + lane * 2) = r;
    }
}

// ---------------------------------------------------------------------------
__global__ void bounds_kernel(const int* __restrict__ batch, int N) {
    int g = threadIdx.x;
    if (g > NGRAPH) return;
    int lo = 0, hi = N;
    while (lo < hi) {
        int mid = (lo + hi) >> 1;
        if (batch[mid] < g) lo = mid + 1; else hi = mid;
    }
    g_gstart[g] = lo;
}

__global__ void pool_kernel() {
    int g = blockIdx.x;
    int t = threadIdx.x;
    int f   = t & 63;
    int sub = t >> 6;
    int s = g_gstart[g], e = g_gstart[g + 1];
    float acc = 0.0f;
    for (int i = s + sub; i < e; i += 4)
        acc += g_h2[(size_t)i * 64 + f];
    __shared__ float red[256];
    red[t] = acc;
    __syncthreads();
    if (t < 64) {
        float v = red[t] + red[t + 64] + red[t + 128] + red[t + 192];
        float cnt = (float)(e - s);
        g_pool[g * 64 + t] = v / fmaxf(cnt, 1.0f);
    }
}

__global__ void fc_kernel(const float* __restrict__ Wfc,
                          const float* __restrict__ bfc,
                          float* __restrict__ out, int flat) {
    int idx = blockIdx.x * blockDim.x + threadIdx.x;
    int tot = NGRAPH * flat;
    if (idx >= tot) return;
    int g = idx / flat;
    int j = idx - g * flat;
    const float* pg = g_pool + g * 64;
    float s = bfc[j];
    #pragma unroll 8
    for (int k = 0; k < 64; k++)
        s = fmaf(pg[k], Wfc[(size_t)k * flat + j], s);
    out[idx] = s;
}

// ---------------------------------------------------------------------------
// Static resources (created at load time — NOT during capture)
// ---------------------------------------------------------------------------
static cudaStream_t g_s2;
static cudaEvent_t  g_evFork, g_evJoin, g_evG1A, g_evGemm2A;
namespace {
struct StreamInit {
    StreamInit() {
        cudaStreamCreateWithFlags(&g_s2, cudaStreamNonBlocking);
        cudaEventCreateWithFlags(&g_evFork, cudaEventDisableTiming);
        cudaEventCreateWithFlags(&g_evJoin, cudaEventDisableTiming);
        cudaEventCreateWithFlags(&g_evG1A, cudaEventDisableTiming);
        cudaEventCreateWithFlags(&g_evGemm2A, cudaEventDisableTiming);
        cudaFuncSetAttribute(wmma_gemm_kernel<128>,
                             cudaFuncAttributeMaxDynamicSharedMemorySize, WMMA_SMEM_128);
        cudaFuncSetAttribute(wmma_gemm_kernel<64>,
                             cudaFuncAttributeMaxDynamicSharedMemorySize, WMMA_SMEM_64);
    }
};
static StreamInit g_streamInit;
}

// ---------------------------------------------------------------------------
extern "C" void kernel_launch(void* const* d_in, const int* in_sizes, int n_in,
                              void* d_out, int out_size) {
    const float* x     = (const float*)d_in[0];
    const int*   ei    = (const int*)d_in[1];
    const float* ew    = (const float*)d_in[2];
    const int*   batch = (const int*)d_in[3];
    const float* W1    = (const float*)d_in[4];
    const float* b1    = (const float*)d_in[5];
    const float* W2    = (const float*)d_in[6];
    const float* b2    = (const float*)d_in[7];
    const float* Wfc   = (const float*)d_in[8];
    const float* bfc   = (const float*)d_in[9];
    float* out = (float*)d_out;

    int N    = in_sizes[0] / 128;   // 40000
    int E    = in_sizes[2];         // 640000
    int flat = in_sizes[8] / 64;    // 2904
    int npart = (N + SCAN_CHUNK - 1) / SCAN_CHUNK;
    int tb = 256;
    int ngrid = (N + 127) / 128;    // 313
    int epairs = (E + 1) / 2;

    int gridA = (ngrid + 1) / 2;    // 157
    int MA    = gridA * 128;        // 20096
    int gridB = ngrid - gridA;      // 156
    int MB    = N - MA;             // 19904

    // ---- fork: GEMM1 + bounds on s2, CSR prologue on default ----
    cudaEventRecord(g_evFork, 0);
    cudaStreamWaitEvent(g_s2, g_evFork, 0);

    bounds_kernel<<<1, 128, 0, g_s2>>>(batch, N);
    wmma_gemm_kernel<128><<<ngrid, 256, WMMA_SMEM_128, g_s2>>>(x, W1, N, 0);

    zero_kernel<<<(N + tb - 1) / tb, tb>>>(N);
    degree_kernel<<<(epairs + tb - 1) / tb, tb>>>(ei, ew, E);
    scan_part_kernel<<<npart, 256>>>(N);
    scan_final_kernel<<<npart, 256>>>(npart, N, E);
    build_kernel<<<(epairs + tb - 1) / tb, tb>>>(ei, ew, E);

    cudaEventRecord(g_evJoin, g_s2);
    cudaStreamWaitEvent(0, g_evJoin, 0);

    // ---- layer 1 aggregate / layer 2 GEMM pipeline ----
    gather_kernel<128><<<(MA + 7) / 8, 256>>>(b1, 0, MA, N);
    cudaEventRecord(g_evG1A, 0);
    cudaStreamWaitEvent(g_s2, g_evG1A, 0);
    wmma_gemm_kernel<64><<<gridA, 256, WMMA_SMEM_64, g_s2>>>(nullptr, W2, N, 0);
    cudaEventRecord(g_evGemm2A, g_s2);

    gather_kernel<128><<<(MB + 7) / 8, 256>>>(b1, MA, MB, N);
    wmma_gemm_kernel<64><<<gridB, 256, WMMA_SMEM_64>>>(nullptr, W2, N, MA);
    cudaStreamWaitEvent(0, g_evGemm2A, 0);

    // ---- layer 2 aggregate, pool, fc ----
    gather_kernel<64><<<(N + 7) / 8, 256>>>(b2, 0, N, N);
    pool_kernel<<<NGRAPH, 256>>>();
    fc_kernel<<<(NGRAPH * flat + tb - 1) / tb, tb>>>(Wfc, bfc, out, flat);
}